// round 2
// baseline (speedup 1.0000x reference)
#include <cuda_runtime.h>

// Problem constants
#define BD   64
#define UV   81
#define HD   96
#define WD   96
#define HW   (HD * WD)          // 9216
#define NPIX (BD * HW)          // 589824

#define INV_LOG49 0.2569487252483261f
#define INV_LOG81 0.2275598569527368f

// blockDim = (32, 4). Each block handles 32 consecutive pixels.
// Warp-row yy handles a contiguous slice of the 81 displacement planes:
//   yy=0 -> planes [0,21), yy=1 -> [21,41), yy=2 -> [41,61), yy=3 -> [61,81)
__global__ __launch_bounds__(128)
void vcn_kernel(const float* __restrict__ x, float* __restrict__ out) {
    const int lane = threadIdx.x;
    const int yy   = threadIdx.y;

    const int pixel = blockIdx.x * 32 + lane;
    const int b  = pixel / HW;
    const int hw = pixel - b * HW;
    const float* px = x + (size_t)b * UV * HW + hw;

    const int start = yy * 20 + (yy > 0 ? 1 : 0);
    const int cnt   = (yy == 0) ? 21 : 20;

    // Load this thread's plane slice (coalesced: lane -> consecutive w).
    float val[21];
#pragma unroll
    for (int k = 0; k < 21; k++) {
        if (k < cnt) val[k] = px[(size_t)(start + k) * HW];
    }

    // ---- Phase 1: partial argmax, combine across the 4 warp-rows ----
    float pm = val[0];
    int   pi = 0;
#pragma unroll
    for (int k = 1; k < 21; k++) {
        if (k < cnt && val[k] > pm) { pm = val[k]; pi = k; }
    }
    pi += start;

    __shared__ float smax[4][32];
    __shared__ int   sidx[4][32];
    __shared__ float spart[6][4][32];

    smax[yy][lane] = pm;
    sidx[yy][lane] = pi;
    __syncthreads();

    float M    = smax[0][lane];
    int   amax = sidx[0][lane];
#pragma unroll
    for (int q = 1; q < 4; q++) {
        float m2 = smax[q][lane];
        // ascending q => ascending plane index; strict > keeps first occurrence
        if (m2 > M) { M = m2; amax = sidx[q][lane]; }
    }

    // 9-bit window masks: bit u set iff |u - iu| <= 3
    const int iu = amax / 9;
    const int iv = amax - iu * 9;
    const unsigned rowbits = (0x7Fu << iu) >> 3;
    const unsigned colbits = (0x7Fu << iv) >> 3;

    // ---- Phase 2: partial moments over this thread's slice ----
    int u = start / 9;            // start in {0,21,41,61} -> u in {0,2,4,6}
    int v = start - u * 9;
    float fu = (float)(u - 4);
    float fv = (float)(v - 4);

    float Sg = 0.f, Tg = 0.f, Sl = 0.f, Tl = 0.f, Sfx = 0.f, Sfy = 0.f;
#pragma unroll
    for (int k = 0; k < 21; k++) {
        if (k < cnt) {
            float d  = val[k] - M;
            float e  = __expf(d);
            float de = d * e;
            Sg += e;
            Tg += de;
            if ((rowbits >> u) & (colbits >> v) & 1u) {
                Sl  += e;
                Tl  += de;
                Sfx += e * fu;
                Sfy += e * fv;
            }
            // advance (u,v) and their float mirrors
            v++; fv += 1.0f;
            if (v == 9) { v = 0; fv = -4.0f; u++; fu += 1.0f; }
        }
    }

    spart[0][yy][lane] = Sg;
    spart[1][yy][lane] = Tg;
    spart[2][yy][lane] = Sl;
    spart[3][yy][lane] = Tl;
    spart[4][yy][lane] = Sfx;
    spart[5][yy][lane] = Sfy;
    __syncthreads();

    // ---- Final combine + output: warp-row 0 only (coalesced stores) ----
    if (yy == 0) {
#pragma unroll
        for (int q = 1; q < 4; q++) {
            Sg  += spart[0][q][lane];
            Tg  += spart[1][q][lane];
            Sl  += spart[2][q][lane];
            Tl  += spart[3][q][lane];
            Sfx += spart[4][q][lane];
            Sfy += spart[5][q][lane];
        }
        float invSl = 1.0f / Sl;
        float invSg = 1.0f / Sg;
        float outx = Sfx * invSl;
        float outy = Sfy * invSl;
        float entl = (__logf(Sl) - Tl * invSl) * INV_LOG49;
        float entg = (__logf(Sg) - Tg * invSg) * INV_LOG81;

        float* o = out + (size_t)b * 4 * HW + hw;
        o[0]      = outx;
        o[HW]     = outy;
        o[2 * HW] = entl;
        o[3 * HW] = entg;
    }
}

extern "C" void kernel_launch(void* const* d_in, const int* in_sizes, int n_in,
                              void* d_out, int out_size) {
    const float* x = (const float*)d_in[0];
    float* out = (float*)d_out;
    dim3 block(32, 4);
    int blocks = NPIX / 32;   // 18432
    vcn_kernel<<<blocks, block>>>(x, out);
}

// round 3
// speedup vs baseline: 1.3412x; 1.3412x over previous
#include <cuda_runtime.h>

#define HW   9216            // 96*96
#define NPIX 589824          // 64*HW

#define INV_LOG49 0.2569487252483261f
#define INV_LOG81 0.2275598569527368f
#define L2E       1.4426950408889634f

__device__ __forceinline__ float ex2(float x) {
    float y;
    asm("ex2.approx.ftz.f32 %0, %1;" : "=f"(y) : "f"(x));
    return y;
}

template<int START, int CNT>
__device__ __forceinline__ void load_argmax(const float* __restrict__ px,
                                            float* val, float& pm, int& pi) {
#pragma unroll
    for (int k = 0; k < CNT; k++)
        val[k] = px[(size_t)(START + k) * HW];
    pm = val[0];
    pi = START;
#pragma unroll
    for (int k = 1; k < CNT; k++)
        if (val[k] > pm) { pm = val[k]; pi = START + k; }
}

template<int START, int CNT>
__device__ __forceinline__ void moments(const float* val, float nML2E,
                                        unsigned rowbits, unsigned colbits,
                                        float* acc) {
#pragma unroll
    for (int k = 0; k < CNT; k++) {
        const int i = START + k;        // compile-time after unroll
        const int u = i / 9;
        const int v = i - u * 9;
        float e = ex2(fmaf(val[k], L2E, nML2E));   // exp(val - M)
        acc[0] += e;                                // Sg
        acc[1] = fmaf(val[k], e, acc[1]);           // T'g = sum val*e
        if ((rowbits >> u) & (colbits >> v) & 1u) {
            acc[2] += e;                            // Sl
            acc[3] = fmaf(val[k], e, acc[3]);       // T'l
            acc[4] = fmaf(e, (float)(u - 4), acc[4]); // Sfx (imm FFMA)
            acc[5] = fmaf(e, (float)(v - 4), acc[5]); // Sfy (imm FFMA)
        }
    }
}

__global__ __launch_bounds__(128)
void vcn_kernel(const float* __restrict__ x, float* __restrict__ out) {
    const int lane = threadIdx.x;
    const int yy   = threadIdx.y;

    const int pixel = blockIdx.x * 32 + lane;
    const int b  = pixel / HW;
    const int hw = pixel - b * HW;
    const float* px = x + (size_t)b * 81 * HW + hw;

    __shared__ float smax[4][32];
    __shared__ int   sidx[4][32];
    __shared__ float spart[6][4][32];

    float val[21];
    float pm;
    int   pi;

    // Phase 1: load slice + partial argmax (compile-time slice bounds)
    switch (yy) {
        case 0:  load_argmax< 0, 21>(px, val, pm, pi); break;
        case 1:  load_argmax<21, 20>(px, val, pm, pi); break;
        case 2:  load_argmax<41, 20>(px, val, pm, pi); break;
        default: load_argmax<61, 20>(px, val, pm, pi); break;
    }
    smax[yy][lane] = pm;
    sidx[yy][lane] = pi;
    __syncthreads();

    // Combine argmax (ascending yy + strict '>' keeps first occurrence)
    float M    = smax[0][lane];
    int   amax = sidx[0][lane];
#pragma unroll
    for (int q = 1; q < 4; q++) {
        float m2 = smax[q][lane];
        if (m2 > M) { M = m2; amax = sidx[q][lane]; }
    }

    const int iu = amax / 9;
    const int iv = amax - iu * 9;
    const unsigned rowbits = (0x7Fu << iu) >> 3;   // bit u set iff |u-iu|<=3
    const unsigned colbits = (0x7Fu << iv) >> 3;

    // Phase 2: partial moments (compile-time u,v per element)
    float acc[6] = {0.f, 0.f, 0.f, 0.f, 0.f, 0.f};
    const float nML2E = -M * L2E;
    switch (yy) {
        case 0:  moments< 0, 21>(val, nML2E, rowbits, colbits, acc); break;
        case 1:  moments<21, 20>(val, nML2E, rowbits, colbits, acc); break;
        case 2:  moments<41, 20>(val, nML2E, rowbits, colbits, acc); break;
        default: moments<61, 20>(val, nML2E, rowbits, colbits, acc); break;
    }
#pragma unroll
    for (int j = 0; j < 6; j++) spart[j][yy][lane] = acc[j];
    __syncthreads();

    // Final combine + output (warp-row 0; coalesced stores)
    if (yy == 0) {
#pragma unroll
        for (int q = 1; q < 4; q++)
#pragma unroll
            for (int j = 0; j < 6; j++) acc[j] += spart[j][q][lane];

        float Sg = acc[0], Tg = acc[1], Sl = acc[2], Tl = acc[3];
        float Sfx = acc[4], Sfy = acc[5];
        float invSl = 1.0f / Sl;
        float invSg = 1.0f / Sg;
        // -sum p log p = log S - sum(val*e)/S + M
        float entl = (__logf(Sl) - Tl * invSl + M) * INV_LOG49;
        float entg = (__logf(Sg) - Tg * invSg + M) * INV_LOG81;

        float* o = out + (size_t)b * 4 * HW + hw;
        o[0]      = Sfx * invSl;
        o[HW]     = Sfy * invSl;
        o[2 * HW] = entl;
        o[3 * HW] = entg;
    }
}

extern "C" void kernel_launch(void* const* d_in, const int* in_sizes, int n_in,
                              void* d_out, int out_size) {
    const float* x = (const float*)d_in[0];
    float* out = (float*)d_out;
    dim3 block(32, 4);
    vcn_kernel<<<NPIX / 32, block>>>(x, out);
}